// round 14
// baseline (speedup 1.0000x reference)
#include <cuda_runtime.h>
#include <cuda_fp16.h>

#define Bb 4
#define Tt 2048
#define Ee 1024
#define Hh 16
#define Dd 64
#define MT (Bb * Tt)   // 8192 rows

typedef unsigned long long ull;
typedef unsigned int u32;

// ---------------- device scratch (allocation-free rule) ----------------
__device__ __align__(16) __half g_x[(size_t)MT * Ee];               // x single fp16
__device__ __align__(16) __half g_wt[(size_t)3 * Hh * Dd * Ee];     // [mat][h*64+d][e], Wq pre-scaled 1/8
__device__ __align__(16) __half g_wot[(size_t)Ee * Ee];             // [n][e] single fp16
__device__ __align__(16) __half g_a[(size_t)MT * Ee];               // attn out, single fp16
// layout [bh][t][d], all single fp16
__device__ __align__(16) __half g_q[(size_t)Bb * Hh * Tt * Dd];
__device__ __align__(16) __half g_k[(size_t)Bb * Hh * Tt * Dd];
__device__ __align__(16) __half g_v[(size_t)Bb * Hh * Tt * Dd];

// ---------------- PTX helpers ----------------
__device__ __forceinline__ u32 smem_u32(const void* p) {
    u32 a;
    asm("{ .reg .u64 t; cvta.to.shared.u64 t, %1; cvt.u32.u64 %0, t; }"
        : "=r"(a) : "l"(p));
    return a;
}
__device__ __forceinline__ void cpa16(u32 dst, const void* src) {
    asm volatile("cp.async.cg.shared.global [%0], [%1], 16;"
                 :: "r"(dst), "l"(src) : "memory");
}
#define CP_COMMIT() asm volatile("cp.async.commit_group;" ::: "memory")
#define CP_WAIT1()  asm volatile("cp.async.wait_group 1;" ::: "memory")
#define CP_WAIT0()  asm volatile("cp.async.wait_group 0;" ::: "memory")

__device__ __forceinline__ void ldsm4(u32 addr, u32& r0, u32& r1, u32& r2, u32& r3) {
    asm volatile("ldmatrix.sync.aligned.m8n8.x4.shared.b16 {%0,%1,%2,%3}, [%4];"
                 : "=r"(r0), "=r"(r1), "=r"(r2), "=r"(r3) : "r"(addr));
}
__device__ __forceinline__ void ldsm4t(u32 addr, u32& r0, u32& r1, u32& r2, u32& r3) {
    asm volatile("ldmatrix.sync.aligned.m8n8.x4.trans.shared.b16 {%0,%1,%2,%3}, [%4];"
                 : "=r"(r0), "=r"(r1), "=r"(r2), "=r"(r3) : "r"(addr));
}
__device__ __forceinline__ void mma16816(float* d, u32 a0, u32 a1, u32 a2, u32 a3,
                                         u32 b0, u32 b1) {
    asm volatile(
        "mma.sync.aligned.m16n8k16.row.col.f32.f16.f16.f32 "
        "{%0,%1,%2,%3},{%4,%5,%6,%7},{%8,%9},{%0,%1,%2,%3};"
        : "+f"(d[0]), "+f"(d[1]), "+f"(d[2]), "+f"(d[3])
        : "r"(a0), "r"(a1), "r"(a2), "r"(a3), "r"(b0), "r"(b1));
}
__device__ __forceinline__ float ex2f(float x) {
    float r; asm("ex2.approx.f32 %0,%1;" : "=f"(r) : "f"(x)); return r;
}
__device__ __forceinline__ u32 pack_f16(__half a, __half b) {
    __half2 t = __halves2half2(a, b);
    return *(u32*)&t;
}

#define L2E 1.4426950408889634f

// ---------------------------------------------------------------------------
// Prep kernels
// ---------------------------------------------------------------------------
__global__ void __launch_bounds__(256) conv_x(const float* __restrict__ x) {
    size_t i = ((size_t)blockIdx.x * 256 + threadIdx.x) * 4;
    float4 v = *(const float4*)&x[i];
    *(u32*)(g_x + i) = pack_f16(__float2half_rn(v.x), __float2half_rn(v.y));
    *(u32*)(g_x + i + 2) = pack_f16(__float2half_rn(v.z), __float2half_rn(v.w));
}

__global__ void __launch_bounds__(256) prep_wqkv(
    const float* __restrict__ Wq, const float* __restrict__ Wk,
    const float* __restrict__ Wv)
{
    __shared__ float tile[32][33];
    int z = blockIdx.z;
    int mat = z >> 4, h = z & 15;
    const float* W = (mat == 0 ? Wq : (mat == 1 ? Wk : Wv)) + (size_t)h * Ee * Dd;
    float scale = (mat == 0) ? 0.125f : 1.0f;   // fold D^-1/2 into Wq
    __half* dst = g_wt + ((size_t)mat * Hh + h) * Dd * Ee;
    int e0 = blockIdx.y << 5, d0 = blockIdx.x << 5;
    int tx = threadIdx.x & 31, ty = threadIdx.x >> 5;
#pragma unroll
    for (int j = 0; j < 4; j++)
        tile[ty + j * 8][tx] = W[(size_t)(e0 + ty + j * 8) * Dd + d0 + tx];
    __syncthreads();
#pragma unroll
    for (int j = 0; j < 4; j++) {
        int rr = ty + j * 8;
        dst[(size_t)(d0 + rr) * Ee + e0 + tx] = __float2half_rn(tile[tx][rr] * scale);
    }
}

__global__ void __launch_bounds__(256) prep_wo(const float* __restrict__ Wo) {
    __shared__ float tile[32][33];
    int n0 = blockIdx.x << 5, e0 = blockIdx.y << 5;
    int tx = threadIdx.x & 31, ty = threadIdx.x >> 5;
#pragma unroll
    for (int j = 0; j < 4; j++)
        tile[ty + j * 8][tx] = Wo[(size_t)(e0 + ty + j * 8) * Ee + n0 + tx];
    __syncthreads();
#pragma unroll
    for (int j = 0; j < 4; j++) {
        int rr = ty + j * 8;
        g_wot[(size_t)(n0 + rr) * Ee + e0 + tx] = __float2half_rn(tile[tx][rr]);
    }
}

// ---------------------------------------------------------------------------
// mma.sync GEMM machinery (3-stage pipelined dense GEMMs)
// ---------------------------------------------------------------------------
#define TILE_B   16384u
#define G1_BUF   32768u
#define G1_SMEM  (3u * G1_BUF)   // 96KB, 2 CTA/SM

__device__ __forceinline__ void copy_tile_async(u32 tb, const __half* sp, int tid) {
#pragma unroll
    for (int it = 0; it < 4; it++) {
        int cid = it * 256 + tid;
        int row = cid >> 3, c = cid & 7;
        u32 dst = tb + (u32)(row << 7) + (u32)(((c ^ (row & 7))) << 4);
        cpa16(dst, sp + (size_t)row * Ee + c * 8);
    }
}
// 256-row contiguous tile (32KB)
__device__ __forceinline__ void copy_tile256(u32 tb, const __half* sp, int tid) {
#pragma unroll
    for (int it = 0; it < 8; it++) {
        int cid = it * 256 + tid;
        int row = cid >> 3, c = cid & 7;
        u32 dst = tb + (u32)(row << 7) + (u32)(((c ^ (row & 7))) << 4);
        cpa16(dst, sp + (size_t)cid * 8);
    }
}
// 64-row contiguous tile (8KB)
__device__ __forceinline__ void copy_tile64(u32 tb, const __half* sp, int tid) {
#pragma unroll
    for (int it = 0; it < 2; it++) {
        int cid = it * 256 + tid;
        int row = cid >> 3, c = cid & 7;
        u32 dst = tb + (u32)(row << 7) + (u32)(((c ^ (row & 7))) << 4);
        cpa16(dst, sp + (size_t)cid * 8);
    }
}

__device__ __forceinline__ void frag_setup(int lane, int Wm, int Wn,
                                           u32* aoff, u32* a7, u32& cA,
                                           u32* boff, u32* b7, u32& cB) {
#pragma unroll
    for (int mt = 0; mt < 4; mt++) {
        int r = Wm + mt * 16 + (lane & 15);
        aoff[mt] = (u32)(r << 7);
        a7[mt] = (u32)(r & 7);
    }
#pragma unroll
    for (int np = 0; np < 2; np++) {
        int r = Wn + np * 16 + ((lane >> 4) << 3) + (lane & 7);
        boff[np] = (u32)(r << 7);
        b7[np] = (u32)(r & 7);
    }
    cA = (u32)(lane >> 4);
    cB = (u32)((lane >> 3) & 1);
}

// 1-pass chunk: single A, single B
__device__ __forceinline__ void gemm_chunk1(
    u32 sA, u32 sB,
    const u32* aoff, const u32* a7, u32 cA,
    const u32* boff, const u32* b7, u32 cB,
    float acc[4][4][4])
{
#pragma unroll
    for (int s = 0; s < 4; s++) {
        u32 a_[4][4], b_[2][4];
#pragma unroll
        for (int mt = 0; mt < 4; mt++) {
            u32 ca = (u32)(((2 * s + cA) ^ a7[mt]) << 4);
            ldsm4(sA + aoff[mt] + ca, a_[mt][0], a_[mt][1], a_[mt][2], a_[mt][3]);
        }
#pragma unroll
        for (int np = 0; np < 2; np++) {
            u32 cb = (u32)(((2 * s + cB) ^ b7[np]) << 4);
            ldsm4(sB + boff[np] + cb, b_[np][0], b_[np][1], b_[np][2], b_[np][3]);
        }
#pragma unroll
        for (int mt = 0; mt < 4; mt++) {
#pragma unroll
            for (int nt = 0; nt < 4; nt++) {
                int np = nt >> 1, sel = (nt & 1) << 1;
                mma16816(acc[mt][nt], a_[mt][0], a_[mt][1], a_[mt][2], a_[mt][3],
                         b_[np][sel], b_[np][sel + 1]);
            }
        }
    }
}

// ---------------------------------------------------------------------------
// QKV projection (1-pass, 3-stage, 2 CTA/SM) -> q/k/v single fp16.
// grid (24, 64), block 256, 96KB smem.
// ---------------------------------------------------------------------------
__global__ void __launch_bounds__(256, 2) qkv_mma() {
    extern __shared__ char smraw[];
    u32 sbase = smem_u32(smraw);

    int tid = threadIdx.x;
    int lane = tid & 31, w = tid >> 5;
    int Wm = (w & 1) << 6, Wn = (w >> 1) << 5;

    int n0 = blockIdx.x << 7;
    int m0 = blockIdx.y << 7;
    int mat = n0 >> 10;
    int nb = n0 & 1023;

    const __half* A = g_x + (size_t)m0 * Ee;
    const __half* Bw = g_wt + (size_t)mat * Hh * Dd * Ee + (size_t)nb * Ee;

    u32 aoff[4], a7[4], boff[2], b7[2], cA, cB;
    frag_setup(lane, Wm, Wn, aoff, a7, cA, boff, b7, cB);

    float acc[4][4][4] = {};

#pragma unroll
    for (int c = 0; c < 2; c++) {
        u32 bu = sbase + (u32)c * G1_BUF;
        copy_tile_async(bu, A + (c << 6), tid);
        copy_tile_async(bu + TILE_B, Bw + (c << 6), tid);
        CP_COMMIT();
    }

    for (int c = 0; c < 16; c++) {
        if (c == 15) { CP_WAIT0(); } else { CP_WAIT1(); }
        __syncthreads();
        if (c < 14) {
            u32 bu = sbase + (u32)((c + 2) % 3) * G1_BUF;
            int k0 = (c + 2) << 6;
            copy_tile_async(bu, A + k0, tid);
            copy_tile_async(bu + TILE_B, Bw + k0, tid);
            CP_COMMIT();
        }
        u32 sb = sbase + (u32)(c % 3) * G1_BUF;
        gemm_chunk1(sb, sb + TILE_B, aoff, a7, cA, boff, b7, cB, acc);
    }

    __half* outp = (mat == 0) ? g_q : (mat == 1) ? g_k : g_v;
#pragma unroll
    for (int mt = 0; mt < 4; mt++) {
#pragma unroll
        for (int nt = 0; nt < 4; nt++) {
            int n = nb + Wn + nt * 8 + ((lane & 3) << 1);
            int h = n >> 6, d = n & 63;
            int m = m0 + Wm + mt * 16 + (lane >> 2);
            int b = m >> 11, t = m & 2047;
            size_t base = (((size_t)(b * Hh + h)) * Tt + t) * Dd + d;
            *(u32*)(outp + base) = pack_f16(__float2half_rn(acc[mt][nt][0]),
                                            __float2half_rn(acc[mt][nt][1]));
            *(u32*)(outp + base + 8 * Dd) = pack_f16(__float2half_rn(acc[mt][nt][2]),
                                                     __float2half_rn(acc[mt][nt][3]));
        }
    }
}

// ---------------------------------------------------------------------------
// Out projection (1-pass, 3-stage, 2 CTA/SM): out = A_f16 * Wo_f16.
// grid (8, 64), block 256.
// ---------------------------------------------------------------------------
__global__ void __launch_bounds__(256, 2) out_mma(float* __restrict__ out) {
    extern __shared__ char smraw[];
    u32 sbase = smem_u32(smraw);

    int tid = threadIdx.x;
    int lane = tid & 31, w = tid >> 5;
    int Wm = (w & 1) << 6, Wn = (w >> 1) << 5;

    int n0 = blockIdx.x << 7;
    int m0 = blockIdx.y << 7;

    const __half* A = g_a + (size_t)m0 * Ee;
    const __half* B = g_wot + (size_t)n0 * Ee;

    u32 aoff[4], a7[4], boff[2], b7[2], cA, cB;
    frag_setup(lane, Wm, Wn, aoff, a7, cA, boff, b7, cB);

    float acc[4][4][4] = {};

#pragma unroll
    for (int c = 0; c < 2; c++) {
        u32 bu = sbase + (u32)c * G1_BUF;
        copy_tile_async(bu, A + (c << 6), tid);
        copy_tile_async(bu + TILE_B, B + (c << 6), tid);
        CP_COMMIT();
    }

    for (int c = 0; c < 16; c++) {
        if (c == 15) { CP_WAIT0(); } else { CP_WAIT1(); }
        __syncthreads();
        if (c < 14) {
            u32 bu = sbase + (u32)((c + 2) % 3) * G1_BUF;
            int k0 = (c + 2) << 6;
            copy_tile_async(bu, A + k0, tid);
            copy_tile_async(bu + TILE_B, B + k0, tid);
            CP_COMMIT();
        }
        u32 sb = sbase + (u32)(c % 3) * G1_BUF;
        gemm_chunk1(sb, sb + TILE_B, aoff, a7, cA, boff, b7, cB, acc);
    }

#pragma unroll
    for (int mt = 0; mt < 4; mt++) {
#pragma unroll
        for (int nt = 0; nt < 4; nt++) {
            int n = n0 + Wn + nt * 8 + ((lane & 3) << 1);
            int m = m0 + Wm + mt * 16 + (lane >> 2);
            *(float2*)&out[(size_t)m * Ee + n] = make_float2(acc[mt][nt][0], acc[mt][nt][1]);
            *(float2*)&out[(size_t)(m + 8) * Ee + n] = make_float2(acc[mt][nt][2], acc[mt][nt][3]);
        }
    }
}

// ---------------------------------------------------------------------------
// FA2-style tensor-core causal flash attention.
// 256-row Q CTA tiles, warp owns 32 q rows (m32); 64-wide K/V tiles.
// K/V fragments amortized over 2x q rows -> crossbar-load per MAC drops 40%.
// grid (8 reversed, 64), block 256, 64KB dynamic smem, 1 CTA/SM.
// ---------------------------------------------------------------------------
#define AQ  0u           // 256 x 64 fp16 = 32KB
#define AK0 32768u
#define AK1 40960u
#define AV0 49152u
#define AV1 57344u
#define ATTN_SMEM 65536u

__global__ void __launch_bounds__(256, 1) attn_mma() {
    extern __shared__ char smraw[];
    u32 sb = smem_u32(smraw);

    int tid = threadIdx.x, lane = tid & 31, w = tid >> 5;
    int qi = (int)gridDim.x - 1 - (int)blockIdx.x;   // 0..7, long blocks first
    int bh = blockIdx.y;
    size_t tbase = (size_t)bh * Tt * Dd;
    const __half* qp = g_q + tbase + ((size_t)qi << 8) * Dd;
    const __half* kp = g_k + tbase;
    const __half* vp = g_v + tbase;

    int Wm = w << 5;   // warp owns q rows [Wm, Wm+32)

    // S A-frags (2x m16 of Q rows)
    u32 aoff[2], a7[2];
#pragma unroll
    for (int mf = 0; mf < 2; mf++) {
        int r = Wm + mf * 16 + (lane & 15);
        aoff[mf] = (u32)(r << 7);
        a7[mf] = (u32)(r & 7);
    }
    u32 cA = (u32)(lane >> 4);
    // S B-frags (K rows 0..63, 4 groups of n16)
    u32 boff[4], b7[4];
#pragma unroll
    for (int np = 0; np < 4; np++) {
        int r = np * 16 + ((lane >> 4) << 3) + (lane & 7);
        boff[np] = (u32)(r << 7);
        b7[np] = (u32)(r & 7);
    }
    u32 cB = (u32)((lane >> 3) & 1);
    // PV V-frags (ldsm4t), V rows 0..63
    int vj = lane >> 3;
    int v_rbase = ((vj & 1) << 3) + (lane & 7);
    u32 v_cb = (u32)(vj >> 1);

    float m_[4] = {-1e30f, -1e30f, -1e30f, -1e30f};
    float l_[4] = {0.f, 0.f, 0.f, 0.f};
    float acc2[2][8][4] = {};

    int njt = 4 * qi + 4;   // number of 64-wide key tiles

    // prologue: Q + K(0) + V(0)
    copy_tile256(sb + AQ, qp, tid);
    copy_tile64(sb + AK0, kp, tid);
    copy_tile64(sb + AV0, vp, tid);
    CP_COMMIT();

    for (int j = 0; j < njt; j++) {
        int buf = j & 1;
        CP_WAIT0();
        __syncthreads();      // K/V(j) visible; all warps done with j-1 buffers

        if (j + 1 < njt) {    // prefetch K/V(j+1) into the other buffers
            copy_tile64(sb + (buf ? AK0 : AK1), kp + ((size_t)(j + 1) << 6) * Dd, tid);
            copy_tile64(sb + (buf ? AV0 : AV1), vp + ((size_t)(j + 1) << 6) * Dd, tid);
            CP_COMMIT();
        }
        u32 sK = sb + (buf ? AK1 : AK0);
        u32 sV = sb + (buf ? AV1 : AV0);

        // ---- S = Q . K^T  (warp: m32 x n64)
        float sacc[2][8][4] = {};
#pragma unroll
        for (int s = 0; s < 4; s++) {
            u32 a_[2][4];
#pragma unroll
            for (int mf = 0; mf < 2; mf++)
                ldsm4(sb + AQ + aoff[mf] + (((2 * (u32)s + cA) ^ a7[mf]) << 4),
                      a_[mf][0], a_[mf][1], a_[mf][2], a_[mf][3]);
#pragma unroll
            for (int np = 0; np < 4; np++) {
                u32 q0, q1, q2, q3;
                ldsm4(sK + boff[np] + (((2 * (u32)s + cB) ^ b7[np]) << 4), q0, q1, q2, q3);
#pragma unroll
                for (int mf = 0; mf < 2; mf++) {
                    mma16816(sacc[mf][2 * np], a_[mf][0], a_[mf][1], a_[mf][2], a_[mf][3], q0, q1);
                    mma16816(sacc[mf][2 * np + 1], a_[mf][0], a_[mf][1], a_[mf][2], a_[mf][3], q2, q3);
                }
            }
        }

        // ---- causal mask (last 4 tiles only)
        if (j >= 4 * qi) {
            int roff = (qi << 8) - (j << 6);   // 0, -64, -128, -192
#pragma unroll
            for (int mf = 0; mf < 2; mf++)
#pragma unroll
                for (int nt = 0; nt < 8; nt++)
#pragma unroll
                    for (int rg = 0; rg < 4; rg++) {
                        int rl = Wm + mf * 16 + (lane >> 2) + ((rg >> 1) << 3);
                        int cl = nt * 8 + ((lane & 3) << 1) + (rg & 1);
                        if (cl > rl + roff) sacc[mf][nt][rg] = -1e30f;
                    }
        }

        // ---- in-warp online softmax; P -> fp16 A-fragments in registers
        u32 paf[2][4][4];
#pragma unroll
        for (int mf = 0; mf < 2; mf++) {
#pragma unroll
            for (int rh = 0; rh < 2; rh++) {
                int mr = mf * 2 + rh;
                float mx = -1e30f;
#pragma unroll
                for (int nt = 0; nt < 8; nt++) {
                    mx = fmaxf(mx, sacc[mf][nt][rh * 2]);
                    mx = fmaxf(mx, sacc[mf][nt][rh * 2 + 1]);
                }
                mx = fmaxf(mx, __shfl_xor_sync(0xffffffffu, mx, 1));
                mx = fmaxf(mx, __shfl_xor_sync(0xffffffffu, mx, 2));
                float mn = fmaxf(m_[mr], mx);
                float sc = ex2f((m_[mr] - mn) * L2E);
                float mnl = mn * L2E;
                float rs = 0.f;
#pragma unroll
                for (int nt = 0; nt < 8; nt++) {
                    float p0 = ex2f(fmaf(sacc[mf][nt][rh * 2], L2E, -mnl));
                    float p1 = ex2f(fmaf(sacc[mf][nt][rh * 2 + 1], L2E, -mnl));
                    rs += p0 + p1;
                    paf[mf][nt >> 1][((nt & 1) << 1) + rh] =
                        pack_f16(__float2half_rn(p0), __float2half_rn(p1));
                }
                rs += __shfl_xor_sync(0xffffffffu, rs, 1);
                rs += __shfl_xor_sync(0xffffffffu, rs, 2);
                l_[mr] = l_[mr] * sc + rs;
                m_[mr] = mn;
#pragma unroll
                for (int ntd = 0; ntd < 8; ntd++) {
                    acc2[mf][ntd][rh * 2] *= sc;
                    acc2[mf][ntd][rh * 2 + 1] *= sc;
                }
            }
        }

        // ---- O += P . V  (P from registers, V via ldsm4t; k=64 -> 4 steps)
#pragma unroll
        for (int s = 0; s < 4; s++) {
            int vrow = (s << 4) + v_rbase;
            u32 vro = (u32)(vrow << 7);
            u32 v7 = (u32)(vrow & 7);
            u32 v_[4][4];
#pragma unroll
            for (int g = 0; g < 4; g++) {
                u32 ch = (((v_cb + 2u * g) ^ v7) << 4);
                ldsm4t(sV + vro + ch, v_[g][0], v_[g][1], v_[g][2], v_[g][3]);
            }
#pragma unroll
            for (int mf = 0; mf < 2; mf++) {
#pragma unroll
                for (int ntd = 0; ntd < 8; ntd++) {
                    int g = ntd >> 1, su = (ntd & 1) << 1;
                    mma16816(acc2[mf][ntd], paf[mf][s][0], paf[mf][s][1],
                             paf[mf][s][2], paf[mf][s][3],
                             v_[g][su], v_[g][su + 1]);
                }
            }
        }
    }

    // ---- epilogue: normalize (l in registers), fp16 write [B*T, H*D]
    int b = bh >> 4, h = bh & 15;
#pragma unroll
    for (int mf = 0; mf < 2; mf++) {
#pragma unroll
        for (int rh = 0; rh < 2; rh++) {
            float inv = 1.0f / l_[mf * 2 + rh];
            int t = (qi << 8) + Wm + mf * 16 + (lane >> 2) + rh * 8;
            size_t rowbase = ((size_t)(b * Tt + t)) * (Hh * Dd) + h * Dd;
#pragma unroll
            for (int ntd = 0; ntd < 8; ntd++) {
                int d = ntd * 8 + ((lane & 3) << 1);
                *(u32*)(g_a + rowbase + d) =
                    pack_f16(__float2half_rn(acc2[mf][ntd][rh * 2] * inv),
                             __float2half_rn(acc2[mf][ntd][rh * 2 + 1] * inv));
            }
        }
    }
}

// ---------------------------------------------------------------------------
extern "C" void kernel_launch(void* const* d_in, const int* in_sizes, int n_in,
                              void* d_out, int out_size) {
    const float* x  = (const float*)d_in[0];
    const float* Wq = (const float*)d_in[1];
    const float* Wk = (const float*)d_in[2];
    const float* Wv = (const float*)d_in[3];
    const float* Wo = (const float*)d_in[4];
    float* out = (float*)d_out;

    cudaFuncSetAttribute(qkv_mma, cudaFuncAttributeMaxDynamicSharedMemorySize, G1_SMEM);
    cudaFuncSetAttribute(out_mma, cudaFuncAttributeMaxDynamicSharedMemorySize, G1_SMEM);
    cudaFuncSetAttribute(attn_mma, cudaFuncAttributeMaxDynamicSharedMemorySize, ATTN_SMEM);

    conv_x<<<8192, 256>>>(x);
    prep_wqkv<<<dim3(2, 32, 48), 256>>>(Wq, Wk, Wv);
    prep_wo<<<dim3(32, 32), 256>>>(Wo);
    qkv_mma<<<dim3(24, 64), 256, G1_SMEM>>>();
    attn_mma<<<dim3(8, Bb * Hh), 256, ATTN_SMEM>>>();
    out_mma<<<dim3(8, 64), 256, G1_SMEM>>>(out);
}

// round 15
// speedup vs baseline: 1.0718x; 1.0718x over previous
#include <cuda_runtime.h>
#include <cuda_fp16.h>

#define Bb 4
#define Tt 2048
#define Ee 1024
#define Hh 16
#define Dd 64
#define MT (Bb * Tt)   // 8192 rows

typedef unsigned long long ull;
typedef unsigned int u32;

// ---------------- device scratch (allocation-free rule) ----------------
__device__ __align__(16) __half g_x[(size_t)MT * Ee];               // x single fp16
__device__ __align__(16) __half g_wt[(size_t)3 * Hh * Dd * Ee];     // [mat][h*64+d][e]; Wq pre-scaled (1/8)*log2e
__device__ __align__(16) __half g_wot[(size_t)Ee * Ee];             // [n][e] single fp16
__device__ __align__(16) __half g_a[(size_t)MT * Ee];               // attn out, single fp16
// layout [bh][t][d], all single fp16
__device__ __align__(16) __half g_q[(size_t)Bb * Hh * Tt * Dd];
__device__ __align__(16) __half g_k[(size_t)Bb * Hh * Tt * Dd];
__device__ __align__(16) __half g_v[(size_t)Bb * Hh * Tt * Dd];

// ---------------- PTX helpers ----------------
__device__ __forceinline__ u32 smem_u32(const void* p) {
    u32 a;
    asm("{ .reg .u64 t; cvta.to.shared.u64 t, %1; cvt.u32.u64 %0, t; }"
        : "=r"(a) : "l"(p));
    return a;
}
__device__ __forceinline__ void cpa16(u32 dst, const void* src) {
    asm volatile("cp.async.cg.shared.global [%0], [%1], 16;"
                 :: "r"(dst), "l"(src) : "memory");
}
#define CP_COMMIT() asm volatile("cp.async.commit_group;" ::: "memory")
#define CP_WAIT1()  asm volatile("cp.async.wait_group 1;" ::: "memory")
#define CP_WAIT0()  asm volatile("cp.async.wait_group 0;" ::: "memory")

__device__ __forceinline__ void ldsm4(u32 addr, u32& r0, u32& r1, u32& r2, u32& r3) {
    asm volatile("ldmatrix.sync.aligned.m8n8.x4.shared.b16 {%0,%1,%2,%3}, [%4];"
                 : "=r"(r0), "=r"(r1), "=r"(r2), "=r"(r3) : "r"(addr));
}
__device__ __forceinline__ void ldsm4t(u32 addr, u32& r0, u32& r1, u32& r2, u32& r3) {
    asm volatile("ldmatrix.sync.aligned.m8n8.x4.trans.shared.b16 {%0,%1,%2,%3}, [%4];"
                 : "=r"(r0), "=r"(r1), "=r"(r2), "=r"(r3) : "r"(addr));
}
__device__ __forceinline__ void mma16816(float* d, u32 a0, u32 a1, u32 a2, u32 a3,
                                         u32 b0, u32 b1) {
    asm volatile(
        "mma.sync.aligned.m16n8k16.row.col.f32.f16.f16.f32 "
        "{%0,%1,%2,%3},{%4,%5,%6,%7},{%8,%9},{%0,%1,%2,%3};"
        : "+f"(d[0]), "+f"(d[1]), "+f"(d[2]), "+f"(d[3])
        : "r"(a0), "r"(a1), "r"(a2), "r"(a3), "r"(b0), "r"(b1));
}
__device__ __forceinline__ float ex2f(float x) {
    float r; asm("ex2.approx.f32 %0,%1;" : "=f"(r) : "f"(x)); return r;
}
// pack two f32 -> half2 in ONE instruction: d.lo = lo, d.hi = hi
__device__ __forceinline__ u32 packf2(float lo, float hi) {
    u32 r; asm("cvt.rn.f16x2.f32 %0, %1, %2;" : "=r"(r) : "f"(hi), "f"(lo)); return r;
}

#define L2E 1.4426950408889634f

// ---------------------------------------------------------------------------
// Merged prep kernel: grid 12288 x 256.
//  bid [0, 8192)      : x fp32 -> fp16
//  bid [8192, 11264)  : Wq/Wk/Wv [h][e][d] -> g_wt [mat][h*64+d][e]
//  bid [11264, 12288) : Wo [e][n] -> g_wot [n][e]
// ---------------------------------------------------------------------------
__global__ void __launch_bounds__(256) prep_all(
    const float* __restrict__ x, const float* __restrict__ Wq,
    const float* __restrict__ Wk, const float* __restrict__ Wv,
    const float* __restrict__ Wo)
{
    __shared__ float tile[32][33];
    int bid = blockIdx.x;
    int tid = threadIdx.x;

    if (bid < 8192) {
        size_t i = ((size_t)bid * 256 + tid) * 4;
        float4 v = *(const float4*)&x[i];
        *(u32*)(g_x + i) = packf2(v.x, v.y);
        *(u32*)(g_x + i + 2) = packf2(v.z, v.w);
        return;
    }

    int tx = tid & 31, ty = tid >> 5;
    if (bid < 11264) {
        int idx = bid - 8192;
        int z = idx >> 6;               // 0..47
        int r = idx & 63;
        int mat = z >> 4, h = z & 15;
        int d0 = (r & 1) << 5;
        int e0 = (r >> 1) << 5;
        const float* W = (mat == 0 ? Wq : (mat == 1 ? Wk : Wv)) + (size_t)h * Ee * Dd;
        float scale = (mat == 0) ? 0.125f * L2E : 1.0f;  // fold D^-1/2 and log2e into Wq
        __half* dst = g_wt + ((size_t)mat * Hh + h) * Dd * Ee;
#pragma unroll
        for (int j = 0; j < 4; j++)
            tile[ty + j * 8][tx] = W[(size_t)(e0 + ty + j * 8) * Dd + d0 + tx];
        __syncthreads();
#pragma unroll
        for (int j = 0; j < 4; j++) {
            int rr = ty + j * 8;
            dst[(size_t)(d0 + rr) * Ee + e0 + tx] = __float2half_rn(tile[tx][rr] * scale);
        }
    } else {
        int idx = bid - 11264;
        int n0 = (idx & 31) << 5;
        int e0 = (idx >> 5) << 5;
#pragma unroll
        for (int j = 0; j < 4; j++)
            tile[ty + j * 8][tx] = Wo[(size_t)(e0 + ty + j * 8) * Ee + n0 + tx];
        __syncthreads();
#pragma unroll
        for (int j = 0; j < 4; j++) {
            int rr = ty + j * 8;
            g_wot[(size_t)(n0 + rr) * Ee + e0 + tx] = __float2half_rn(tile[tx][rr]);
        }
    }
}

// ---------------------------------------------------------------------------
// mma.sync GEMM machinery (3-stage pipelined dense GEMMs)
// ---------------------------------------------------------------------------
#define TILE_B   16384u
#define G1_BUF   32768u
#define G1_SMEM  (3u * G1_BUF)   // 96KB, 2 CTA/SM

__device__ __forceinline__ void copy_tile_async(u32 tb, const __half* sp, int tid) {
#pragma unroll
    for (int it = 0; it < 4; it++) {
        int cid = it * 256 + tid;
        int row = cid >> 3, c = cid & 7;
        u32 dst = tb + (u32)(row << 7) + (u32)(((c ^ (row & 7))) << 4);
        cpa16(dst, sp + (size_t)row * Ee + c * 8);
    }
}
__device__ __forceinline__ void copy_tile_c(u32 tb, const __half* sp, int tid) {
#pragma unroll
    for (int it = 0; it < 4; it++) {
        int cid = it * 256 + tid;
        int row = cid >> 3, c = cid & 7;
        u32 dst = tb + (u32)(row << 7) + (u32)(((c ^ (row & 7))) << 4);
        cpa16(dst, sp + (size_t)cid * 8);
    }
}

__device__ __forceinline__ void frag_setup(int lane, int Wm, int Wn,
                                           u32* aoff, u32* a7, u32& cA,
                                           u32* boff, u32* b7, u32& cB) {
#pragma unroll
    for (int mt = 0; mt < 4; mt++) {
        int r = Wm + mt * 16 + (lane & 15);
        aoff[mt] = (u32)(r << 7);
        a7[mt] = (u32)(r & 7);
    }
#pragma unroll
    for (int np = 0; np < 2; np++) {
        int r = Wn + np * 16 + ((lane >> 4) << 3) + (lane & 7);
        boff[np] = (u32)(r << 7);
        b7[np] = (u32)(r & 7);
    }
    cA = (u32)(lane >> 4);
    cB = (u32)((lane >> 3) & 1);
}

// 1-pass chunk: single A, single B
__device__ __forceinline__ void gemm_chunk1(
    u32 sA, u32 sB,
    const u32* aoff, const u32* a7, u32 cA,
    const u32* boff, const u32* b7, u32 cB,
    float acc[4][4][4])
{
#pragma unroll
    for (int s = 0; s < 4; s++) {
        u32 a_[4][4], b_[2][4];
#pragma unroll
        for (int mt = 0; mt < 4; mt++) {
            u32 ca = (u32)(((2 * s + cA) ^ a7[mt]) << 4);
            ldsm4(sA + aoff[mt] + ca, a_[mt][0], a_[mt][1], a_[mt][2], a_[mt][3]);
        }
#pragma unroll
        for (int np = 0; np < 2; np++) {
            u32 cb = (u32)(((2 * s + cB) ^ b7[np]) << 4);
            ldsm4(sB + boff[np] + cb, b_[np][0], b_[np][1], b_[np][2], b_[np][3]);
        }
#pragma unroll
        for (int mt = 0; mt < 4; mt++) {
#pragma unroll
            for (int nt = 0; nt < 4; nt++) {
                int np = nt >> 1, sel = (nt & 1) << 1;
                mma16816(acc[mt][nt], a_[mt][0], a_[mt][1], a_[mt][2], a_[mt][3],
                         b_[np][sel], b_[np][sel + 1]);
            }
        }
    }
}

// ---------------------------------------------------------------------------
// QKV projection (1-pass, 3-stage, 2 CTA/SM) -> q/k/v single fp16.
// grid (24, 64), block 256, 96KB smem.
// ---------------------------------------------------------------------------
__global__ void __launch_bounds__(256, 2) qkv_mma() {
    extern __shared__ char smraw[];
    u32 sbase = smem_u32(smraw);

    int tid = threadIdx.x;
    int lane = tid & 31, w = tid >> 5;
    int Wm = (w & 1) << 6, Wn = (w >> 1) << 5;

    int n0 = blockIdx.x << 7;
    int m0 = blockIdx.y << 7;
    int mat = n0 >> 10;
    int nb = n0 & 1023;

    const __half* A = g_x + (size_t)m0 * Ee;
    const __half* Bw = g_wt + (size_t)mat * Hh * Dd * Ee + (size_t)nb * Ee;

    u32 aoff[4], a7[4], boff[2], b7[2], cA, cB;
    frag_setup(lane, Wm, Wn, aoff, a7, cA, boff, b7, cB);

    float acc[4][4][4] = {};

#pragma unroll
    for (int c = 0; c < 2; c++) {
        u32 bu = sbase + (u32)c * G1_BUF;
        copy_tile_async(bu, A + (c << 6), tid);
        copy_tile_async(bu + TILE_B, Bw + (c << 6), tid);
        CP_COMMIT();
    }

    for (int c = 0; c < 16; c++) {
        if (c == 15) { CP_WAIT0(); } else { CP_WAIT1(); }
        __syncthreads();
        if (c < 14) {
            u32 bu = sbase + (u32)((c + 2) % 3) * G1_BUF;
            int k0 = (c + 2) << 6;
            copy_tile_async(bu, A + k0, tid);
            copy_tile_async(bu + TILE_B, Bw + k0, tid);
            CP_COMMIT();
        }
        u32 sb = sbase + (u32)(c % 3) * G1_BUF;
        gemm_chunk1(sb, sb + TILE_B, aoff, a7, cA, boff, b7, cB, acc);
    }

    __half* outp = (mat == 0) ? g_q : (mat == 1) ? g_k : g_v;
#pragma unroll
    for (int mt = 0; mt < 4; mt++) {
#pragma unroll
        for (int nt = 0; nt < 4; nt++) {
            int n = nb + Wn + nt * 8 + ((lane & 3) << 1);
            int h = n >> 6, d = n & 63;
            int m = m0 + Wm + mt * 16 + (lane >> 2);
            int b = m >> 11, t = m & 2047;
            size_t base = (((size_t)(b * Hh + h)) * Tt + t) * Dd + d;
            *(u32*)(outp + base) = packf2(acc[mt][nt][0], acc[mt][nt][1]);
            *(u32*)(outp + base + 8 * Dd) = packf2(acc[mt][nt][2], acc[mt][nt][3]);
        }
    }
}

// ---------------------------------------------------------------------------
// Out projection (1-pass, 3-stage, 2 CTA/SM): out = A_f16 * Wo_f16.
// grid (8, 64), block 256.
// ---------------------------------------------------------------------------
__global__ void __launch_bounds__(256, 2) out_mma(float* __restrict__ out) {
    extern __shared__ char smraw[];
    u32 sbase = smem_u32(smraw);

    int tid = threadIdx.x;
    int lane = tid & 31, w = tid >> 5;
    int Wm = (w & 1) << 6, Wn = (w >> 1) << 5;

    int n0 = blockIdx.x << 7;
    int m0 = blockIdx.y << 7;

    const __half* A = g_a + (size_t)m0 * Ee;
    const __half* B = g_wot + (size_t)n0 * Ee;

    u32 aoff[4], a7[4], boff[2], b7[2], cA, cB;
    frag_setup(lane, Wm, Wn, aoff, a7, cA, boff, b7, cB);

    float acc[4][4][4] = {};

#pragma unroll
    for (int c = 0; c < 2; c++) {
        u32 bu = sbase + (u32)c * G1_BUF;
        copy_tile_async(bu, A + (c << 6), tid);
        copy_tile_async(bu + TILE_B, B + (c << 6), tid);
        CP_COMMIT();
    }

    for (int c = 0; c < 16; c++) {
        if (c == 15) { CP_WAIT0(); } else { CP_WAIT1(); }
        __syncthreads();
        if (c < 14) {
            u32 bu = sbase + (u32)((c + 2) % 3) * G1_BUF;
            int k0 = (c + 2) << 6;
            copy_tile_async(bu, A + k0, tid);
            copy_tile_async(bu + TILE_B, B + k0, tid);
            CP_COMMIT();
        }
        u32 sb = sbase + (u32)(c % 3) * G1_BUF;
        gemm_chunk1(sb, sb + TILE_B, aoff, a7, cA, boff, b7, cB, acc);
    }

#pragma unroll
    for (int mt = 0; mt < 4; mt++) {
#pragma unroll
        for (int nt = 0; nt < 4; nt++) {
            int n = n0 + Wn + nt * 8 + ((lane & 3) << 1);
            int m = m0 + Wm + mt * 16 + (lane >> 2);
            *(float2*)&out[(size_t)m * Ee + n] = make_float2(acc[mt][nt][0], acc[mt][nt][1]);
            *(float2*)&out[(size_t)(m + 8) * Ee + n] = make_float2(acc[mt][nt][2], acc[mt][nt][3]);
        }
    }
}

// ---------------------------------------------------------------------------
// FA2-style tensor-core causal flash attention (R11 shape: m16 x n128).
// Scores arrive in log2 domain (L2E folded into Wq) -> exp is 1 ex2, no fmaf.
// P packed via cvt.rn.f16x2 (1 instr / pair).
// grid (16 reversed, 64), block 256, 80KB dynamic smem.
// ---------------------------------------------------------------------------
#define AQ  0u
#define AK0 16384u
#define AK1 32768u
#define AV0 49152u
#define AV1 65536u
#define ATTN_SMEM 81920u

__global__ void __launch_bounds__(256, 1) attn_mma() {
    extern __shared__ char smraw[];
    u32 sb = smem_u32(smraw);

    int tid = threadIdx.x, lane = tid & 31, w = tid >> 5;
    int qi = (int)gridDim.x - 1 - (int)blockIdx.x;
    int bh = blockIdx.y;
    size_t tbase = (size_t)bh * Tt * Dd;
    const __half* qp = g_q + tbase + ((size_t)qi << 7) * Dd;
    const __half* kp = g_k + tbase;
    const __half* vp = g_v + tbase;

    int Wm = w << 4;   // warp owns q rows [Wm, Wm+16)

    // S A-frag (Q rows)
    int ar = Wm + (lane & 15);
    u32 aoff = (u32)(ar << 7), a7 = (u32)(ar & 7);
    u32 cA = (u32)(lane >> 4);
    // S B-frags (K rows 0..127, 8 groups of n16)
    u32 boff[8], b7[8];
#pragma unroll
    for (int np = 0; np < 8; np++) {
        int r = np * 16 + ((lane >> 4) << 3) + (lane & 7);
        boff[np] = (u32)(r << 7);
        b7[np] = (u32)(r & 7);
    }
    u32 cB = (u32)((lane >> 3) & 1);
    // PV V-frags (ldsm4t)
    int vj = lane >> 3;
    int v_rbase = ((vj & 1) << 3) + (lane & 7);
    u32 v_cb = (u32)(vj >> 1);

    float m_[2] = {-1e30f, -1e30f};
    float l_[2] = {0.f, 0.f};
    float acc2[8][4] = {};

    // prologue: Q + K(0) + V(0)
    copy_tile_c(sb + AQ, qp, tid);
    copy_tile_c(sb + AK0, kp, tid);
    copy_tile_c(sb + AV0, vp, tid);
    CP_COMMIT();

    for (int j = 0; j <= qi; j++) {
        int buf = j & 1;
        CP_WAIT0();
        __syncthreads();      // K/V(j) visible; all warps done with j-1 buffers

        if (j < qi) {         // prefetch K/V(j+1) into the other buffers
            copy_tile_c(sb + (buf ? AK0 : AK1), kp + ((size_t)(j + 1) << 7) * Dd, tid);
            copy_tile_c(sb + (buf ? AV0 : AV1), vp + ((size_t)(j + 1) << 7) * Dd, tid);
            CP_COMMIT();
        }
        u32 sK = sb + (buf ? AK1 : AK0);
        u32 sV = sb + (buf ? AV1 : AV0);

        // ---- S = Q . K^T  (warp: m16 x n128), scores in log2 domain
        float sacc[16][4] = {};
#pragma unroll
        for (int s = 0; s < 4; s++) {
            u32 a0, a1, a2, a3;
            ldsm4(sb + AQ + aoff + (((2 * (u32)s + cA) ^ a7) << 4), a0, a1, a2, a3);
#pragma unroll
            for (int np = 0; np < 8; np++) {
                u32 q0, q1, q2, q3;
                ldsm4(sK + boff[np] + (((2 * (u32)s + cB) ^ b7[np]) << 4), q0, q1, q2, q3);
                mma16816(sacc[2 * np], a0, a1, a2, a3, q0, q1);
                mma16816(sacc[2 * np + 1], a0, a1, a2, a3, q2, q3);
            }
        }

        // ---- causal mask on diagonal tile
        if (j == qi) {
#pragma unroll
            for (int nt = 0; nt < 16; nt++)
#pragma unroll
                for (int rg = 0; rg < 4; rg++) {
                    int r = Wm + (lane >> 2) + ((rg >> 1) << 3);
                    int c = nt * 8 + ((lane & 3) << 1) + (rg & 1);
                    if (c > r) sacc[nt][rg] = -1e30f;
                }
        }

        // ---- in-warp online softmax (log2 domain); P -> fp16 frags
        u32 paf[8][4];
#pragma unroll
        for (int rh = 0; rh < 2; rh++) {
            float mx = -1e30f;
#pragma unroll
            for (int nt = 0; nt < 16; nt++) {
                mx = fmaxf(mx, sacc[nt][rh * 2]);
                mx = fmaxf(mx, sacc[nt][rh * 2 + 1]);
            }
            mx = fmaxf(mx, __shfl_xor_sync(0xffffffffu, mx, 1));
            mx = fmaxf(mx, __shfl_xor_sync(0xffffffffu, mx, 2));
            float mn = fmaxf(m_[rh], mx);
            float sc = ex2f(m_[rh] - mn);
            float rs = 0.f;
#pragma unroll
            for (int nt = 0; nt < 16; nt++) {
                float p0 = ex2f(sacc[nt][rh * 2] - mn);
                float p1 = ex2f(sacc[nt][rh * 2 + 1] - mn);
                rs += p0 + p1;
                paf[nt >> 1][((nt & 1) << 1) + rh] = packf2(p0, p1);
            }
            rs += __shfl_xor_sync(0xffffffffu, rs, 1);
            rs += __shfl_xor_sync(0xffffffffu, rs, 2);
            l_[rh] = l_[rh] * sc + rs;
            m_[rh] = mn;
#pragma unroll
            for (int ntd = 0; ntd < 8; ntd++) {
                acc2[ntd][rh * 2] *= sc;
                acc2[ntd][rh * 2 + 1] *= sc;
            }
        }

        // ---- O += P . V  (P from registers, V via ldsm4t)
#pragma unroll
        for (int s = 0; s < 8; s++) {
            int vrow = (s << 4) + v_rbase;
            u32 vro = (u32)(vrow << 7);
            u32 v7 = (u32)(vrow & 7);
            u32 v_[4][4];
#pragma unroll
            for (int g = 0; g < 4; g++) {
                u32 ch = (((v_cb + 2u * g) ^ v7) << 4);
                ldsm4t(sV + vro + ch, v_[g][0], v_[g][1], v_[g][2], v_[g][3]);
            }
#pragma unroll
            for (int ntd = 0; ntd < 8; ntd++) {
                int g = ntd >> 1, su = (ntd & 1) << 1;
                mma16816(acc2[ntd], paf[s][0], paf[s][1], paf[s][2], paf[s][3],
                         v_[g][su], v_[g][su + 1]);
            }
        }
    }

    // ---- epilogue: normalize (l in registers), fp16 write [B*T, H*D]
    int b = bh >> 4, h = bh & 15;
#pragma unroll
    for (int rh = 0; rh < 2; rh++) {
        float inv = 1.0f / l_[rh];
        int t = (qi << 7) + Wm + (lane >> 2) + rh * 8;
        size_t rowbase = ((size_t)(b * Tt + t)) * (Hh * Dd) + h * Dd;
#pragma unroll
        for (int ntd = 0; ntd < 8; ntd++) {
            int d = ntd * 8 + ((lane & 3) << 1);
            *(u32*)(g_a + rowbase + d) =
                packf2(acc2[ntd][rh * 2] * inv, acc2[ntd][rh * 2 + 1] * inv);
        }
    }
}

// ---------------------------------------------------------------------------
extern "C" void kernel_launch(void* const* d_in, const int* in_sizes, int n_in,
                              void* d_out, int out_size) {
    const float* x  = (const float*)d_in[0];
    const float* Wq = (const float*)d_in[1];
    const float* Wk = (const float*)d_in[2];
    const float* Wv = (const float*)d_in[3];
    const float* Wo = (const float*)d_in[4];
    float* out = (float*)d_out;

    cudaFuncSetAttribute(qkv_mma, cudaFuncAttributeMaxDynamicSharedMemorySize, G1_SMEM);
    cudaFuncSetAttribute(out_mma, cudaFuncAttributeMaxDynamicSharedMemorySize, G1_SMEM);
    cudaFuncSetAttribute(attn_mma, cudaFuncAttributeMaxDynamicSharedMemorySize, ATTN_SMEM);

    prep_all<<<12288, 256>>>(x, Wq, Wk, Wv, Wo);
    qkv_mma<<<dim3(24, 64), 256, G1_SMEM>>>();
    attn_mma<<<dim3(Tt / 128, Bb * Hh), 256, ATTN_SMEM>>>();
    out_mma<<<dim3(8, 64), 256, G1_SMEM>>>(out);
}

// round 16
// speedup vs baseline: 1.0990x; 1.0254x over previous
#include <cuda_runtime.h>
#include <cuda_fp16.h>

#define Bb 4
#define Tt 2048
#define Ee 1024
#define Hh 16
#define Dd 64
#define MT (Bb * Tt)   // 8192 rows

typedef unsigned long long ull;
typedef unsigned int u32;

// ---------------- device scratch (allocation-free rule) ----------------
__device__ __align__(16) __half g_x[(size_t)MT * Ee];               // x single fp16
__device__ __align__(16) __half g_wt[(size_t)3 * Hh * Dd * Ee];     // [mat][h*64+d][e]; Wq pre-scaled (1/8)*log2e
__device__ __align__(16) __half g_wot[(size_t)Ee * Ee];             // [n][e] single fp16
__device__ __align__(16) __half g_a[(size_t)MT * Ee];               // attn out, single fp16
// layout [bh][t][d], all single fp16
__device__ __align__(16) __half g_q[(size_t)Bb * Hh * Tt * Dd];
__device__ __align__(16) __half g_k[(size_t)Bb * Hh * Tt * Dd];
__device__ __align__(16) __half g_v[(size_t)Bb * Hh * Tt * Dd];

// ---------------- PTX helpers ----------------
__device__ __forceinline__ u32 smem_u32(const void* p) {
    u32 a;
    asm("{ .reg .u64 t; cvta.to.shared.u64 t, %1; cvt.u32.u64 %0, t; }"
        : "=r"(a) : "l"(p));
    return a;
}
__device__ __forceinline__ void cpa16(u32 dst, const void* src) {
    asm volatile("cp.async.cg.shared.global [%0], [%1], 16;"
                 :: "r"(dst), "l"(src) : "memory");
}
#define CP_COMMIT() asm volatile("cp.async.commit_group;" ::: "memory")
#define CP_WAIT1()  asm volatile("cp.async.wait_group 1;" ::: "memory")
#define CP_WAIT0()  asm volatile("cp.async.wait_group 0;" ::: "memory")

__device__ __forceinline__ void ldsm4(u32 addr, u32& r0, u32& r1, u32& r2, u32& r3) {
    asm volatile("ldmatrix.sync.aligned.m8n8.x4.shared.b16 {%0,%1,%2,%3}, [%4];"
                 : "=r"(r0), "=r"(r1), "=r"(r2), "=r"(r3) : "r"(addr));
}
__device__ __forceinline__ void ldsm4t(u32 addr, u32& r0, u32& r1, u32& r2, u32& r3) {
    asm volatile("ldmatrix.sync.aligned.m8n8.x4.trans.shared.b16 {%0,%1,%2,%3}, [%4];"
                 : "=r"(r0), "=r"(r1), "=r"(r2), "=r"(r3) : "r"(addr));
}
__device__ __forceinline__ void mma16816(float* d, u32 a0, u32 a1, u32 a2, u32 a3,
                                         u32 b0, u32 b1) {
    asm volatile(
        "mma.sync.aligned.m16n8k16.row.col.f32.f16.f16.f32 "
        "{%0,%1,%2,%3},{%4,%5,%6,%7},{%8,%9},{%0,%1,%2,%3};"
        : "+f"(d[0]), "+f"(d[1]), "+f"(d[2]), "+f"(d[3])
        : "r"(a0), "r"(a1), "r"(a2), "r"(a3), "r"(b0), "r"(b1));
}
__device__ __forceinline__ float ex2f(float x) {
    float r; asm("ex2.approx.f32 %0,%1;" : "=f"(r) : "f"(x)); return r;
}
// ex2 on packed half2 (one MUFU op for two values)
__device__ __forceinline__ u32 hex2(u32 x) {
    u32 r; asm("ex2.approx.f16x2 %0,%1;" : "=r"(r) : "r"(x)); return r;
}
// pack two f32 -> half2 in ONE instruction: d.lo = lo, d.hi = hi
__device__ __forceinline__ u32 packf2(float lo, float hi) {
    u32 r; asm("cvt.rn.f16x2.f32 %0, %1, %2;" : "=r"(r) : "f"(hi), "f"(lo)); return r;
}

#define L2E 1.4426950408889634f
#define ONES2 0x3C003C00u   // half2(1.0, 1.0)

// ---------------------------------------------------------------------------
// Merged prep kernel: grid 12288 x 256.
// ---------------------------------------------------------------------------
__global__ void __launch_bounds__(256) prep_all(
    const float* __restrict__ x, const float* __restrict__ Wq,
    const float* __restrict__ Wk, const float* __restrict__ Wv,
    const float* __restrict__ Wo)
{
    __shared__ float tile[32][33];
    int bid = blockIdx.x;
    int tid = threadIdx.x;

    if (bid < 8192) {
        size_t i = ((size_t)bid * 256 + tid) * 4;
        float4 v = *(const float4*)&x[i];
        *(u32*)(g_x + i) = packf2(v.x, v.y);
        *(u32*)(g_x + i + 2) = packf2(v.z, v.w);
        return;
    }

    int tx = tid & 31, ty = tid >> 5;
    if (bid < 11264) {
        int idx = bid - 8192;
        int z = idx >> 6;
        int r = idx & 63;
        int mat = z >> 4, h = z & 15;
        int d0 = (r & 1) << 5;
        int e0 = (r >> 1) << 5;
        const float* W = (mat == 0 ? Wq : (mat == 1 ? Wk : Wv)) + (size_t)h * Ee * Dd;
        float scale = (mat == 0) ? 0.125f * L2E : 1.0f;
        __half* dst = g_wt + ((size_t)mat * Hh + h) * Dd * Ee;
#pragma unroll
        for (int j = 0; j < 4; j++)
            tile[ty + j * 8][tx] = W[(size_t)(e0 + ty + j * 8) * Dd + d0 + tx];
        __syncthreads();
#pragma unroll
        for (int j = 0; j < 4; j++) {
            int rr = ty + j * 8;
            dst[(size_t)(d0 + rr) * Ee + e0 + tx] = __float2half_rn(tile[tx][rr] * scale);
        }
    } else {
        int idx = bid - 11264;
        int n0 = (idx & 31) << 5;
        int e0 = (idx >> 5) << 5;
#pragma unroll
        for (int j = 0; j < 4; j++)
            tile[ty + j * 8][tx] = Wo[(size_t)(e0 + ty + j * 8) * Ee + n0 + tx];
        __syncthreads();
#pragma unroll
        for (int j = 0; j < 4; j++) {
            int rr = ty + j * 8;
            g_wot[(size_t)(n0 + rr) * Ee + e0 + tx] = __float2half_rn(tile[tx][rr]);
        }
    }
}

// ---------------------------------------------------------------------------
// mma.sync GEMM machinery (3-stage pipelined dense GEMMs)
// ---------------------------------------------------------------------------
#define TILE_B   16384u
#define G1_BUF   32768u
#define G1_SMEM  (3u * G1_BUF)   // 96KB, 2 CTA/SM

__device__ __forceinline__ void copy_tile_async(u32 tb, const __half* sp, int tid) {
#pragma unroll
    for (int it = 0; it < 4; it++) {
        int cid = it * 256 + tid;
        int row = cid >> 3, c = cid & 7;
        u32 dst = tb + (u32)(row << 7) + (u32)(((c ^ (row & 7))) << 4);
        cpa16(dst, sp + (size_t)row * Ee + c * 8);
    }
}
__device__ __forceinline__ void copy_tile_c(u32 tb, const __half* sp, int tid) {
#pragma unroll
    for (int it = 0; it < 4; it++) {
        int cid = it * 256 + tid;
        int row = cid >> 3, c = cid & 7;
        u32 dst = tb + (u32)(row << 7) + (u32)(((c ^ (row & 7))) << 4);
        cpa16(dst, sp + (size_t)cid * 8);
    }
}

__device__ __forceinline__ void frag_setup(int lane, int Wm, int Wn,
                                           u32* aoff, u32* a7, u32& cA,
                                           u32* boff, u32* b7, u32& cB) {
#pragma unroll
    for (int mt = 0; mt < 4; mt++) {
        int r = Wm + mt * 16 + (lane & 15);
        aoff[mt] = (u32)(r << 7);
        a7[mt] = (u32)(r & 7);
    }
#pragma unroll
    for (int np = 0; np < 2; np++) {
        int r = Wn + np * 16 + ((lane >> 4) << 3) + (lane & 7);
        boff[np] = (u32)(r << 7);
        b7[np] = (u32)(r & 7);
    }
    cA = (u32)(lane >> 4);
    cB = (u32)((lane >> 3) & 1);
}

// 1-pass chunk: single A, single B
__device__ __forceinline__ void gemm_chunk1(
    u32 sA, u32 sB,
    const u32* aoff, const u32* a7, u32 cA,
    const u32* boff, const u32* b7, u32 cB,
    float acc[4][4][4])
{
#pragma unroll
    for (int s = 0; s < 4; s++) {
        u32 a_[4][4], b_[2][4];
#pragma unroll
        for (int mt = 0; mt < 4; mt++) {
            u32 ca = (u32)(((2 * s + cA) ^ a7[mt]) << 4);
            ldsm4(sA + aoff[mt] + ca, a_[mt][0], a_[mt][1], a_[mt][2], a_[mt][3]);
        }
#pragma unroll
        for (int np = 0; np < 2; np++) {
            u32 cb = (u32)(((2 * s + cB) ^ b7[np]) << 4);
            ldsm4(sB + boff[np] + cb, b_[np][0], b_[np][1], b_[np][2], b_[np][3]);
        }
#pragma unroll
        for (int mt = 0; mt < 4; mt++) {
#pragma unroll
            for (int nt = 0; nt < 4; nt++) {
                int np = nt >> 1, sel = (nt & 1) << 1;
                mma16816(acc[mt][nt], a_[mt][0], a_[mt][1], a_[mt][2], a_[mt][3],
                         b_[np][sel], b_[np][sel + 1]);
            }
        }
    }
}

// ---------------------------------------------------------------------------
// QKV projection (1-pass, 3-stage, 2 CTA/SM) -> q/k/v single fp16.
// grid (24, 64), block 256, 96KB smem.
// ---------------------------------------------------------------------------
__global__ void __launch_bounds__(256, 2) qkv_mma() {
    extern __shared__ char smraw[];
    u32 sbase = smem_u32(smraw);

    int tid = threadIdx.x;
    int lane = tid & 31, w = tid >> 5;
    int Wm = (w & 1) << 6, Wn = (w >> 1) << 5;

    int n0 = blockIdx.x << 7;
    int m0 = blockIdx.y << 7;
    int mat = n0 >> 10;
    int nb = n0 & 1023;

    const __half* A = g_x + (size_t)m0 * Ee;
    const __half* Bw = g_wt + (size_t)mat * Hh * Dd * Ee + (size_t)nb * Ee;

    u32 aoff[4], a7[4], boff[2], b7[2], cA, cB;
    frag_setup(lane, Wm, Wn, aoff, a7, cA, boff, b7, cB);

    float acc[4][4][4] = {};

#pragma unroll
    for (int c = 0; c < 2; c++) {
        u32 bu = sbase + (u32)c * G1_BUF;
        copy_tile_async(bu, A + (c << 6), tid);
        copy_tile_async(bu + TILE_B, Bw + (c << 6), tid);
        CP_COMMIT();
    }

    for (int c = 0; c < 16; c++) {
        if (c == 15) { CP_WAIT0(); } else { CP_WAIT1(); }
        __syncthreads();
        if (c < 14) {
            u32 bu = sbase + (u32)((c + 2) % 3) * G1_BUF;
            int k0 = (c + 2) << 6;
            copy_tile_async(bu, A + k0, tid);
            copy_tile_async(bu + TILE_B, Bw + k0, tid);
            CP_COMMIT();
        }
        u32 sb = sbase + (u32)(c % 3) * G1_BUF;
        gemm_chunk1(sb, sb + TILE_B, aoff, a7, cA, boff, b7, cB, acc);
    }

    __half* outp = (mat == 0) ? g_q : (mat == 1) ? g_k : g_v;
#pragma unroll
    for (int mt = 0; mt < 4; mt++) {
#pragma unroll
        for (int nt = 0; nt < 4; nt++) {
            int n = nb + Wn + nt * 8 + ((lane & 3) << 1);
            int h = n >> 6, d = n & 63;
            int m = m0 + Wm + mt * 16 + (lane >> 2);
            int b = m >> 11, t = m & 2047;
            size_t base = (((size_t)(b * Hh + h)) * Tt + t) * Dd + d;
            *(u32*)(outp + base) = packf2(acc[mt][nt][0], acc[mt][nt][1]);
            *(u32*)(outp + base + 8 * Dd) = packf2(acc[mt][nt][2], acc[mt][nt][3]);
        }
    }
}

// ---------------------------------------------------------------------------
// Out projection (1-pass, 3-stage, 2 CTA/SM): out = A_f16 * Wo_f16.
// grid (8, 64), block 256.
// ---------------------------------------------------------------------------
__global__ void __launch_bounds__(256, 2) out_mma(float* __restrict__ out) {
    extern __shared__ char smraw[];
    u32 sbase = smem_u32(smraw);

    int tid = threadIdx.x;
    int lane = tid & 31, w = tid >> 5;
    int Wm = (w & 1) << 6, Wn = (w >> 1) << 5;

    int n0 = blockIdx.x << 7;
    int m0 = blockIdx.y << 7;

    const __half* A = g_a + (size_t)m0 * Ee;
    const __half* B = g_wot + (size_t)n0 * Ee;

    u32 aoff[4], a7[4], boff[2], b7[2], cA, cB;
    frag_setup(lane, Wm, Wn, aoff, a7, cA, boff, b7, cB);

    float acc[4][4][4] = {};

#pragma unroll
    for (int c = 0; c < 2; c++) {
        u32 bu = sbase + (u32)c * G1_BUF;
        copy_tile_async(bu, A + (c << 6), tid);
        copy_tile_async(bu + TILE_B, B + (c << 6), tid);
        CP_COMMIT();
    }

    for (int c = 0; c < 16; c++) {
        if (c == 15) { CP_WAIT0(); } else { CP_WAIT1(); }
        __syncthreads();
        if (c < 14) {
            u32 bu = sbase + (u32)((c + 2) % 3) * G1_BUF;
            int k0 = (c + 2) << 6;
            copy_tile_async(bu, A + k0, tid);
            copy_tile_async(bu + TILE_B, B + k0, tid);
            CP_COMMIT();
        }
        u32 sb = sbase + (u32)(c % 3) * G1_BUF;
        gemm_chunk1(sb, sb + TILE_B, aoff, a7, cA, boff, b7, cB, acc);
    }

#pragma unroll
    for (int mt = 0; mt < 4; mt++) {
#pragma unroll
        for (int nt = 0; nt < 4; nt++) {
            int n = n0 + Wn + nt * 8 + ((lane & 3) << 1);
            int m = m0 + Wm + mt * 16 + (lane >> 2);
            *(float2*)&out[(size_t)m * Ee + n] = make_float2(acc[mt][nt][0], acc[mt][nt][1]);
            *(float2*)&out[(size_t)(m + 8) * Ee + n] = make_float2(acc[mt][nt][2], acc[mt][nt][3]);
        }
    }
}

// ---------------------------------------------------------------------------
// FA2-style tensor-core causal flash attention (m16 x n128 warp tiles).
// Log2-domain scores; ex2.approx.f16x2 softmax (output IS the P fragment);
// row sums via extra ones-column MMA (l lives in fp32 accumulators).
// grid (16 reversed, 64), block 256, 80KB dynamic smem.
// ---------------------------------------------------------------------------
#define AQ  0u
#define AK0 16384u
#define AK1 32768u
#define AV0 49152u
#define AV1 65536u
#define ATTN_SMEM 81920u

__global__ void __launch_bounds__(256, 1) attn_mma() {
    extern __shared__ char smraw[];
    u32 sb = smem_u32(smraw);

    int tid = threadIdx.x, lane = tid & 31, w = tid >> 5;
    int qi = (int)gridDim.x - 1 - (int)blockIdx.x;
    int bh = blockIdx.y;
    size_t tbase = (size_t)bh * Tt * Dd;
    const __half* qp = g_q + tbase + ((size_t)qi << 7) * Dd;
    const __half* kp = g_k + tbase;
    const __half* vp = g_v + tbase;

    int Wm = w << 4;   // warp owns q rows [Wm, Wm+16)

    // S A-frag (Q rows)
    int ar = Wm + (lane & 15);
    u32 aoff = (u32)(ar << 7), a7 = (u32)(ar & 7);
    u32 cA = (u32)(lane >> 4);
    // S B-frags (K rows 0..127, 8 groups of n16)
    u32 boff[8], b7[8];
#pragma unroll
    for (int np = 0; np < 8; np++) {
        int r = np * 16 + ((lane >> 4) << 3) + (lane & 7);
        boff[np] = (u32)(r << 7);
        b7[np] = (u32)(r & 7);
    }
    u32 cB = (u32)((lane >> 3) & 1);
    // PV V-frags (ldsm4t)
    int vj = lane >> 3;
    int v_rbase = ((vj & 1) << 3) + (lane & 7);
    u32 v_cb = (u32)(vj >> 1);

    float m_[2] = {-1e30f, -1e30f};
    float lacc[4] = {0.f, 0.f, 0.f, 0.f};   // row-sum accumulator (ones-MMA)
    float acc2[8][4] = {};

    // prologue: Q + K(0) + V(0)
    copy_tile_c(sb + AQ, qp, tid);
    copy_tile_c(sb + AK0, kp, tid);
    copy_tile_c(sb + AV0, vp, tid);
    CP_COMMIT();

    for (int j = 0; j <= qi; j++) {
        int buf = j & 1;
        CP_WAIT0();
        __syncthreads();      // K/V(j) visible; all warps done with j-1 buffers

        if (j < qi) {         // prefetch K/V(j+1) into the other buffers
            copy_tile_c(sb + (buf ? AK0 : AK1), kp + ((size_t)(j + 1) << 7) * Dd, tid);
            copy_tile_c(sb + (buf ? AV0 : AV1), vp + ((size_t)(j + 1) << 7) * Dd, tid);
            CP_COMMIT();
        }
        u32 sK = sb + (buf ? AK1 : AK0);
        u32 sV = sb + (buf ? AV1 : AV0);

        // ---- S = Q . K^T  (warp: m16 x n128), scores in log2 domain
        float sacc[16][4] = {};
#pragma unroll
        for (int s = 0; s < 4; s++) {
            u32 a0, a1, a2, a3;
            ldsm4(sb + AQ + aoff + (((2 * (u32)s + cA) ^ a7) << 4), a0, a1, a2, a3);
#pragma unroll
            for (int np = 0; np < 8; np++) {
                u32 q0, q1, q2, q3;
                ldsm4(sK + boff[np] + (((2 * (u32)s + cB) ^ b7[np]) << 4), q0, q1, q2, q3);
                mma16816(sacc[2 * np], a0, a1, a2, a3, q0, q1);
                mma16816(sacc[2 * np + 1], a0, a1, a2, a3, q2, q3);
            }
        }

        // ---- causal mask on diagonal tile
        if (j == qi) {
#pragma unroll
            for (int nt = 0; nt < 16; nt++)
#pragma unroll
                for (int rg = 0; rg < 4; rg++) {
                    int r = Wm + (lane >> 2) + ((rg >> 1) << 3);
                    int c = nt * 8 + ((lane & 3) << 1) + (rg & 1);
                    if (c > r) sacc[nt][rg] = -1e30f;
                }
        }

        // ---- in-warp online softmax (log2 domain, f16x2 exp)
        u32 paf[8][4];
#pragma unroll
        for (int rh = 0; rh < 2; rh++) {
            float mx = -1e30f;
#pragma unroll
            for (int nt = 0; nt < 16; nt++) {
                mx = fmaxf(mx, sacc[nt][rh * 2]);
                mx = fmaxf(mx, sacc[nt][rh * 2 + 1]);
            }
            mx = fmaxf(mx, __shfl_xor_sync(0xffffffffu, mx, 1));
            mx = fmaxf(mx, __shfl_xor_sync(0xffffffffu, mx, 2));
            float mn = fmaxf(m_[rh], mx);
            float sc = ex2f(m_[rh] - mn);
            m_[rh] = mn;
#pragma unroll
            for (int nt = 0; nt < 16; nt++) {
                // subtract in f32, pack, one f16x2 ex2 -> directly the P fragment
                paf[nt >> 1][((nt & 1) << 1) + rh] =
                    hex2(packf2(sacc[nt][rh * 2] - mn, sacc[nt][rh * 2 + 1] - mn));
            }
            // rescale O and l accumulators
#pragma unroll
            for (int ntd = 0; ntd < 8; ntd++) {
                acc2[ntd][rh * 2] *= sc;
                acc2[ntd][rh * 2 + 1] *= sc;
            }
            lacc[rh * 2] *= sc;
            lacc[rh * 2 + 1] *= sc;
        }

        // ---- O += P . V ; l += P . 1  (P from registers, V via ldsm4t)
#pragma unroll
        for (int s = 0; s < 8; s++) {
            int vrow = (s << 4) + v_rbase;
            u32 vro = (u32)(vrow << 7);
            u32 v7 = (u32)(vrow & 7);
            u32 v_[4][4];
#pragma unroll
            for (int g = 0; g < 4; g++) {
                u32 ch = (((v_cb + 2u * g) ^ v7) << 4);
                ldsm4t(sV + vro + ch, v_[g][0], v_[g][1], v_[g][2], v_[g][3]);
            }
            // row-sum column (all-ones B)
            mma16816(lacc, paf[s][0], paf[s][1], paf[s][2], paf[s][3], ONES2, ONES2);
#pragma unroll
            for (int ntd = 0; ntd < 8; ntd++) {
                int g = ntd >> 1, su = (ntd & 1) << 1;
                mma16816(acc2[ntd], paf[s][0], paf[s][1], paf[s][2], paf[s][3],
                         v_[g][su], v_[g][su + 1]);
            }
        }
    }

    // ---- epilogue: normalize (l from ones-MMA accumulator), fp16 write
    int b = bh >> 4, h = bh & 15;
#pragma unroll
    for (int rh = 0; rh < 2; rh++) {
        float inv = 1.0f / lacc[rh * 2];
        int t = (qi << 7) + Wm + (lane >> 2) + rh * 8;
        size_t rowbase = ((size_t)(b * Tt + t)) * (Hh * Dd) + h * Dd;
#pragma unroll
        for (int ntd = 0; ntd < 8; ntd++) {
            int d = ntd * 8 + ((lane & 3) << 1);
            *(u32*)(g_a + rowbase + d) =
                packf2(acc2[ntd][rh * 2] * inv, acc2[ntd][rh * 2 + 1] * inv);
        }
    }
}

// ---------------------------------------------------------------------------
extern "C" void kernel_launch(void* const* d_in, const int* in_sizes, int n_in,
                              void* d_out, int out_size) {
    const float* x  = (const float*)d_in[0];
    const float* Wq = (const float*)d_in[1];
    const float* Wk = (const float*)d_in[2];
    const float* Wv = (const float*)d_in[3];
    const float* Wo = (const float*)d_in[4];
    float* out = (float*)d_out;

    cudaFuncSetAttribute(qkv_mma, cudaFuncAttributeMaxDynamicSharedMemorySize, G1_SMEM);
    cudaFuncSetAttribute(out_mma, cudaFuncAttributeMaxDynamicSharedMemorySize, G1_SMEM);
    cudaFuncSetAttribute(attn_mma, cudaFuncAttributeMaxDynamicSharedMemorySize, ATTN_SMEM);

    prep_all<<<12288, 256>>>(x, Wq, Wk, Wv, Wo);
    qkv_mma<<<dim3(24, 64), 256, G1_SMEM>>>();
    attn_mma<<<dim3(Tt / 128, Bb * Hh), 256, ATTN_SMEM>>>();
    out_mma<<<dim3(8, 64), 256, G1_SMEM>>>(out);
}

// round 17
// speedup vs baseline: 1.1210x; 1.0200x over previous
#include <cuda_runtime.h>
#include <cuda_fp16.h>

#define Bb 4
#define Tt 2048
#define Ee 1024
#define Hh 16
#define Dd 64
#define MT (Bb * Tt)   // 8192 rows

typedef unsigned long long ull;
typedef unsigned int u32;

// ---------------- device scratch (allocation-free rule) ----------------
__device__ __align__(16) __half g_x[(size_t)MT * Ee];               // x single fp16
__device__ __align__(16) __half g_wt[(size_t)3 * Hh * Dd * Ee];     // [mat][h*64+d][e]; Wq pre-scaled (1/8)*log2e
__device__ __align__(16) __half g_wot[(size_t)Ee * Ee];             // [n][e] single fp16
__device__ __align__(16) __half g_a[(size_t)MT * Ee];               // attn out, single fp16
// layout [bh][t][d], all single fp16
__device__ __align__(16) __half g_q[(size_t)Bb * Hh * Tt * Dd];
__device__ __align__(16) __half g_k[(size_t)Bb * Hh * Tt * Dd];
__device__ __align__(16) __half g_v[(size_t)Bb * Hh * Tt * Dd];

// ---------------- PTX helpers ----------------
__device__ __forceinline__ u32 smem_u32(const void* p) {
    u32 a;
    asm("{ .reg .u64 t; cvta.to.shared.u64 t, %1; cvt.u32.u64 %0, t; }"
        : "=r"(a) : "l"(p));
    return a;
}
__device__ __forceinline__ void cpa16(u32 dst, const void* src) {
    asm volatile("cp.async.cg.shared.global [%0], [%1], 16;"
                 :: "r"(dst), "l"(src) : "memory");
}
#define CP_COMMIT() asm volatile("cp.async.commit_group;" ::: "memory")
#define CP_WAIT1()  asm volatile("cp.async.wait_group 1;" ::: "memory")
#define CP_WAIT0()  asm volatile("cp.async.wait_group 0;" ::: "memory")

__device__ __forceinline__ void ldsm4(u32 addr, u32& r0, u32& r1, u32& r2, u32& r3) {
    asm volatile("ldmatrix.sync.aligned.m8n8.x4.shared.b16 {%0,%1,%2,%3}, [%4];"
                 : "=r"(r0), "=r"(r1), "=r"(r2), "=r"(r3) : "r"(addr));
}
__device__ __forceinline__ void ldsm4t(u32 addr, u32& r0, u32& r1, u32& r2, u32& r3) {
    asm volatile("ldmatrix.sync.aligned.m8n8.x4.trans.shared.b16 {%0,%1,%2,%3}, [%4];"
                 : "=r"(r0), "=r"(r1), "=r"(r2), "=r"(r3) : "r"(addr));
}
__device__ __forceinline__ void mma16816(float* d, u32 a0, u32 a1, u32 a2, u32 a3,
                                         u32 b0, u32 b1) {
    asm volatile(
        "mma.sync.aligned.m16n8k16.row.col.f32.f16.f16.f32 "
        "{%0,%1,%2,%3},{%4,%5,%6,%7},{%8,%9},{%0,%1,%2,%3};"
        : "+f"(d[0]), "+f"(d[1]), "+f"(d[2]), "+f"(d[3])
        : "r"(a0), "r"(a1), "r"(a2), "r"(a3), "r"(b0), "r"(b1));
}
__device__ __forceinline__ float ex2f(float x) {
    float r; asm("ex2.approx.f32 %0,%1;" : "=f"(r) : "f"(x)); return r;
}
// ex2 on packed half2 (one MUFU op for two values)
__device__ __forceinline__ u32 hex2(u32 x) {
    u32 r; asm("ex2.approx.f16x2 %0,%1;" : "=r"(r) : "r"(x)); return r;
}
// pack two f32 -> half2 in ONE instruction: d.lo = lo, d.hi = hi
__device__ __forceinline__ u32 packf2(float lo, float hi) {
    u32 r; asm("cvt.rn.f16x2.f32 %0, %1, %2;" : "=r"(r) : "f"(hi), "f"(lo)); return r;
}

#define L2E 1.4426950408889634f
#define ONES2 0x3C003C00u   // half2(1.0, 1.0)

// ---------------------------------------------------------------------------
// Merged prep kernel: grid 12288 x 256.
// ---------------------------------------------------------------------------
__global__ void __launch_bounds__(256) prep_all(
    const float* __restrict__ x, const float* __restrict__ Wq,
    const float* __restrict__ Wk, const float* __restrict__ Wv,
    const float* __restrict__ Wo)
{
    __shared__ float tile[32][33];
    int bid = blockIdx.x;
    int tid = threadIdx.x;

    if (bid < 8192) {
        size_t i = ((size_t)bid * 256 + tid) * 4;
        float4 v = *(const float4*)&x[i];
        *(u32*)(g_x + i) = packf2(v.x, v.y);
        *(u32*)(g_x + i + 2) = packf2(v.z, v.w);
        return;
    }

    int tx = tid & 31, ty = tid >> 5;
    if (bid < 11264) {
        int idx = bid - 8192;
        int z = idx >> 6;
        int r = idx & 63;
        int mat = z >> 4, h = z & 15;
        int d0 = (r & 1) << 5;
        int e0 = (r >> 1) << 5;
        const float* W = (mat == 0 ? Wq : (mat == 1 ? Wk : Wv)) + (size_t)h * Ee * Dd;
        float scale = (mat == 0) ? 0.125f * L2E : 1.0f;
        __half* dst = g_wt + ((size_t)mat * Hh + h) * Dd * Ee;
#pragma unroll
        for (int j = 0; j < 4; j++)
            tile[ty + j * 8][tx] = W[(size_t)(e0 + ty + j * 8) * Dd + d0 + tx];
        __syncthreads();
#pragma unroll
        for (int j = 0; j < 4; j++) {
            int rr = ty + j * 8;
            dst[(size_t)(d0 + rr) * Ee + e0 + tx] = __float2half_rn(tile[tx][rr] * scale);
        }
    } else {
        int idx = bid - 11264;
        int n0 = (idx & 31) << 5;
        int e0 = (idx >> 5) << 5;
#pragma unroll
        for (int j = 0; j < 4; j++)
            tile[ty + j * 8][tx] = Wo[(size_t)(e0 + ty + j * 8) * Ee + n0 + tx];
        __syncthreads();
#pragma unroll
        for (int j = 0; j < 4; j++) {
            int rr = ty + j * 8;
            g_wot[(size_t)(n0 + rr) * Ee + e0 + tx] = __float2half_rn(tile[tx][rr]);
        }
    }
}

// ---------------------------------------------------------------------------
// mma.sync GEMM machinery (3-stage pipelined dense GEMMs)
// ---------------------------------------------------------------------------
#define TILE_B   16384u
#define G1_BUF   32768u
#define G1_SMEM  (3u * G1_BUF)   // 96KB, 2 CTA/SM

__device__ __forceinline__ void copy_tile_async(u32 tb, const __half* sp, int tid) {
#pragma unroll
    for (int it = 0; it < 4; it++) {
        int cid = it * 256 + tid;
        int row = cid >> 3, c = cid & 7;
        u32 dst = tb + (u32)(row << 7) + (u32)(((c ^ (row & 7))) << 4);
        cpa16(dst, sp + (size_t)row * Ee + c * 8);
    }
}
__device__ __forceinline__ void copy_tile_c(u32 tb, const __half* sp, int tid) {
#pragma unroll
    for (int it = 0; it < 4; it++) {
        int cid = it * 256 + tid;
        int row = cid >> 3, c = cid & 7;
        u32 dst = tb + (u32)(row << 7) + (u32)(((c ^ (row & 7))) << 4);
        cpa16(dst, sp + (size_t)cid * 8);
    }
}

__device__ __forceinline__ void frag_setup(int lane, int Wm, int Wn,
                                           u32* aoff, u32* a7, u32& cA,
                                           u32* boff, u32* b7, u32& cB) {
#pragma unroll
    for (int mt = 0; mt < 4; mt++) {
        int r = Wm + mt * 16 + (lane & 15);
        aoff[mt] = (u32)(r << 7);
        a7[mt] = (u32)(r & 7);
    }
#pragma unroll
    for (int np = 0; np < 2; np++) {
        int r = Wn + np * 16 + ((lane >> 4) << 3) + (lane & 7);
        boff[np] = (u32)(r << 7);
        b7[np] = (u32)(r & 7);
    }
    cA = (u32)(lane >> 4);
    cB = (u32)((lane >> 3) & 1);
}

// 1-pass chunk: single A, single B
__device__ __forceinline__ void gemm_chunk1(
    u32 sA, u32 sB,
    const u32* aoff, const u32* a7, u32 cA,
    const u32* boff, const u32* b7, u32 cB,
    float acc[4][4][4])
{
#pragma unroll
    for (int s = 0; s < 4; s++) {
        u32 a_[4][4], b_[2][4];
#pragma unroll
        for (int mt = 0; mt < 4; mt++) {
            u32 ca = (u32)(((2 * s + cA) ^ a7[mt]) << 4);
            ldsm4(sA + aoff[mt] + ca, a_[mt][0], a_[mt][1], a_[mt][2], a_[mt][3]);
        }
#pragma unroll
        for (int np = 0; np < 2; np++) {
            u32 cb = (u32)(((2 * s + cB) ^ b7[np]) << 4);
            ldsm4(sB + boff[np] + cb, b_[np][0], b_[np][1], b_[np][2], b_[np][3]);
        }
#pragma unroll
        for (int mt = 0; mt < 4; mt++) {
#pragma unroll
            for (int nt = 0; nt < 4; nt++) {
                int np = nt >> 1, sel = (nt & 1) << 1;
                mma16816(acc[mt][nt], a_[mt][0], a_[mt][1], a_[mt][2], a_[mt][3],
                         b_[np][sel], b_[np][sel + 1]);
            }
        }
    }
}

// ---------------------------------------------------------------------------
// QKV projection (1-pass, 3-stage, 2 CTA/SM) -> q/k/v single fp16.
// grid (24, 64), block 256, 96KB smem.
// ---------------------------------------------------------------------------
__global__ void __launch_bounds__(256, 2) qkv_mma() {
    extern __shared__ char smraw[];
    u32 sbase = smem_u32(smraw);

    int tid = threadIdx.x;
    int lane = tid & 31, w = tid >> 5;
    int Wm = (w & 1) << 6, Wn = (w >> 1) << 5;

    int n0 = blockIdx.x << 7;
    int m0 = blockIdx.y << 7;
    int mat = n0 >> 10;
    int nb = n0 & 1023;

    const __half* A = g_x + (size_t)m0 * Ee;
    const __half* Bw = g_wt + (size_t)mat * Hh * Dd * Ee + (size_t)nb * Ee;

    u32 aoff[4], a7[4], boff[2], b7[2], cA, cB;
    frag_setup(lane, Wm, Wn, aoff, a7, cA, boff, b7, cB);

    float acc[4][4][4] = {};

#pragma unroll
    for (int c = 0; c < 2; c++) {
        u32 bu = sbase + (u32)c * G1_BUF;
        copy_tile_async(bu, A + (c << 6), tid);
        copy_tile_async(bu + TILE_B, Bw + (c << 6), tid);
        CP_COMMIT();
    }

    for (int c = 0; c < 16; c++) {
        if (c == 15) { CP_WAIT0(); } else { CP_WAIT1(); }
        __syncthreads();
        if (c < 14) {
            u32 bu = sbase + (u32)((c + 2) % 3) * G1_BUF;
            int k0 = (c + 2) << 6;
            copy_tile_async(bu, A + k0, tid);
            copy_tile_async(bu + TILE_B, Bw + k0, tid);
            CP_COMMIT();
        }
        u32 sb = sbase + (u32)(c % 3) * G1_BUF;
        gemm_chunk1(sb, sb + TILE_B, aoff, a7, cA, boff, b7, cB, acc);
    }

    __half* outp = (mat == 0) ? g_q : (mat == 1) ? g_k : g_v;
#pragma unroll
    for (int mt = 0; mt < 4; mt++) {
#pragma unroll
        for (int nt = 0; nt < 4; nt++) {
            int n = nb + Wn + nt * 8 + ((lane & 3) << 1);
            int h = n >> 6, d = n & 63;
            int m = m0 + Wm + mt * 16 + (lane >> 2);
            int b = m >> 11, t = m & 2047;
            size_t base = (((size_t)(b * Hh + h)) * Tt + t) * Dd + d;
            *(u32*)(outp + base) = packf2(acc[mt][nt][0], acc[mt][nt][1]);
            *(u32*)(outp + base + 8 * Dd) = packf2(acc[mt][nt][2], acc[mt][nt][3]);
        }
    }
}

// ---------------------------------------------------------------------------
// Out projection (1-pass, 3-stage, 2 CTA/SM): out = A_f16 * Wo_f16.
// grid (8, 64), block 256.
// ---------------------------------------------------------------------------
__global__ void __launch_bounds__(256, 2) out_mma(float* __restrict__ out) {
    extern __shared__ char smraw[];
    u32 sbase = smem_u32(smraw);

    int tid = threadIdx.x;
    int lane = tid & 31, w = tid >> 5;
    int Wm = (w & 1) << 6, Wn = (w >> 1) << 5;

    int n0 = blockIdx.x << 7;
    int m0 = blockIdx.y << 7;

    const __half* A = g_a + (size_t)m0 * Ee;
    const __half* B = g_wot + (size_t)n0 * Ee;

    u32 aoff[4], a7[4], boff[2], b7[2], cA, cB;
    frag_setup(lane, Wm, Wn, aoff, a7, cA, boff, b7, cB);

    float acc[4][4][4] = {};

#pragma unroll
    for (int c = 0; c < 2; c++) {
        u32 bu = sbase + (u32)c * G1_BUF;
        copy_tile_async(bu, A + (c << 6), tid);
        copy_tile_async(bu + TILE_B, B + (c << 6), tid);
        CP_COMMIT();
    }

    for (int c = 0; c < 16; c++) {
        if (c == 15) { CP_WAIT0(); } else { CP_WAIT1(); }
        __syncthreads();
        if (c < 14) {
            u32 bu = sbase + (u32)((c + 2) % 3) * G1_BUF;
            int k0 = (c + 2) << 6;
            copy_tile_async(bu, A + k0, tid);
            copy_tile_async(bu + TILE_B, B + k0, tid);
            CP_COMMIT();
        }
        u32 sb = sbase + (u32)(c % 3) * G1_BUF;
        gemm_chunk1(sb, sb + TILE_B, aoff, a7, cA, boff, b7, cB, acc);
    }

#pragma unroll
    for (int mt = 0; mt < 4; mt++) {
#pragma unroll
        for (int nt = 0; nt < 4; nt++) {
            int n = n0 + Wn + nt * 8 + ((lane & 3) << 1);
            int m = m0 + Wm + mt * 16 + (lane >> 2);
            *(float2*)&out[(size_t)m * Ee + n] = make_float2(acc[mt][nt][0], acc[mt][nt][1]);
            *(float2*)&out[(size_t)(m + 8) * Ee + n] = make_float2(acc[mt][nt][2], acc[mt][nt][3]);
        }
    }
}

// ---------------------------------------------------------------------------
// FA2-style tensor-core causal flash attention, 2 CTA/SM.
// 128-wide K/V tiles (loads/syncs unchanged), but S processed in two n64
// register halves (S-half -> softmax -> PV-half) so live regs fit the
// 128-reg cap of 2 CTAs/SM. Log2-domain scores, f16x2 exp, ones-MMA rowsum.
// grid (16 reversed, 64), block 256, 80KB dynamic smem.
// ---------------------------------------------------------------------------
#define AQ  0u
#define AK0 16384u
#define AK1 32768u
#define AV0 49152u
#define AV1 65536u
#define ATTN_SMEM 81920u

__global__ void __launch_bounds__(256, 2) attn_mma() {
    extern __shared__ char smraw[];
    u32 sb = smem_u32(smraw);

    int tid = threadIdx.x, lane = tid & 31, w = tid >> 5;
    int qi = (int)gridDim.x - 1 - (int)blockIdx.x;
    int bh = blockIdx.y;
    size_t tbase = (size_t)bh * Tt * Dd;
    const __half* qp = g_q + tbase + ((size_t)qi << 7) * Dd;
    const __half* kp = g_k + tbase;
    const __half* vp = g_v + tbase;

    int Wm = w << 4;   // warp owns q rows [Wm, Wm+16)

    // S A-frag (Q rows)
    int ar = Wm + (lane & 15);
    u32 aoff = (u32)(ar << 7), a7 = (u32)(ar & 7);
    u32 cA = (u32)(lane >> 4);
    // S B-frags (K rows 0..127, 8 groups of n16; half h uses np = 4h..4h+3)
    u32 boff[8], b7[8];
#pragma unroll
    for (int np = 0; np < 8; np++) {
        int r = np * 16 + ((lane >> 4) << 3) + (lane & 7);
        boff[np] = (u32)(r << 7);
        b7[np] = (u32)(r & 7);
    }
    u32 cB = (u32)((lane >> 3) & 1);
    // PV V-frags (ldsm4t)
    int vj = lane >> 3;
    int v_rbase = ((vj & 1) << 3) + (lane & 7);
    u32 v_cb = (u32)(vj >> 1);

    float m_[2] = {-1e30f, -1e30f};
    float lacc[4] = {0.f, 0.f, 0.f, 0.f};
    float acc2[8][4] = {};

    // prologue: Q + K(0) + V(0)
    copy_tile_c(sb + AQ, qp, tid);
    copy_tile_c(sb + AK0, kp, tid);
    copy_tile_c(sb + AV0, vp, tid);
    CP_COMMIT();

    for (int j = 0; j <= qi; j++) {
        int buf = j & 1;
        CP_WAIT0();
        __syncthreads();      // K/V(j) visible; all warps done with j-1 buffers

        if (j < qi) {         // prefetch K/V(j+1) into the other buffers
            copy_tile_c(sb + (buf ? AK0 : AK1), kp + ((size_t)(j + 1) << 7) * Dd, tid);
            copy_tile_c(sb + (buf ? AV0 : AV1), vp + ((size_t)(j + 1) << 7) * Dd, tid);
            CP_COMMIT();
        }
        u32 sK = sb + (buf ? AK1 : AK0);
        u32 sV = sb + (buf ? AV1 : AV0);

#pragma unroll
        for (int hv = 0; hv < 2; hv++) {
            // ---- S-half = Q . K^T  (warp: m16 x n64), log2 domain
            float sacc[8][4] = {};
#pragma unroll
            for (int s = 0; s < 4; s++) {
                u32 a0, a1, a2, a3;
                ldsm4(sb + AQ + aoff + (((2 * (u32)s + cA) ^ a7) << 4), a0, a1, a2, a3);
#pragma unroll
                for (int nl = 0; nl < 4; nl++) {
                    int np = hv * 4 + nl;
                    u32 q0, q1, q2, q3;
                    ldsm4(sK + boff[np] + (((2 * (u32)s + cB) ^ b7[np]) << 4),
                          q0, q1, q2, q3);
                    mma16816(sacc[2 * nl], a0, a1, a2, a3, q0, q1);
                    mma16816(sacc[2 * nl + 1], a0, a1, a2, a3, q2, q3);
                }
            }

            // ---- causal mask (diagonal tile only)
            if (j == qi) {
#pragma unroll
                for (int nt = 0; nt < 8; nt++)
#pragma unroll
                    for (int rg = 0; rg < 4; rg++) {
                        int r = Wm + (lane >> 2) + ((rg >> 1) << 3);
                        int c = (hv << 6) + nt * 8 + ((lane & 3) << 1) + (rg & 1);
                        if (c > r) sacc[nt][rg] = -1e30f;
                    }
            }

            // ---- in-warp online softmax (log2 domain, f16x2 exp)
            u32 paf[4][4];
#pragma unroll
            for (int rh = 0; rh < 2; rh++) {
                float mx = -1e30f;
#pragma unroll
                for (int nt = 0; nt < 8; nt++) {
                    mx = fmaxf(mx, sacc[nt][rh * 2]);
                    mx = fmaxf(mx, sacc[nt][rh * 2 + 1]);
                }
                mx = fmaxf(mx, __shfl_xor_sync(0xffffffffu, mx, 1));
                mx = fmaxf(mx, __shfl_xor_sync(0xffffffffu, mx, 2));
                float mn = fmaxf(m_[rh], mx);
                float sc = ex2f(m_[rh] - mn);
                m_[rh] = mn;
#pragma unroll
                for (int nt = 0; nt < 8; nt++) {
                    paf[nt >> 1][((nt & 1) << 1) + rh] =
                        hex2(packf2(sacc[nt][rh * 2] - mn, sacc[nt][rh * 2 + 1] - mn));
                }
#pragma unroll
                for (int ntd = 0; ntd < 8; ntd++) {
                    acc2[ntd][rh * 2] *= sc;
                    acc2[ntd][rh * 2 + 1] *= sc;
                }
                lacc[rh * 2] *= sc;
                lacc[rh * 2 + 1] *= sc;
            }

            // ---- O += P_half . V_half ; l += P_half . 1
#pragma unroll
            for (int s = 0; s < 4; s++) {
                int vrow = (hv << 6) + (s << 4) + v_rbase;
                u32 vro = (u32)(vrow << 7);
                u32 v7 = (u32)(vrow & 7);
                u32 v_[4][4];
#pragma unroll
                for (int g = 0; g < 4; g++) {
                    u32 ch = (((v_cb + 2u * g) ^ v7) << 4);
                    ldsm4t(sV + vro + ch, v_[g][0], v_[g][1], v_[g][2], v_[g][3]);
                }
                mma16816(lacc, paf[s][0], paf[s][1], paf[s][2], paf[s][3], ONES2, ONES2);
#pragma unroll
                for (int ntd = 0; ntd < 8; ntd++) {
                    int g = ntd >> 1, su = (ntd & 1) << 1;
                    mma16816(acc2[ntd], paf[s][0], paf[s][1], paf[s][2], paf[s][3],
                             v_[g][su], v_[g][su + 1]);
                }
            }
        }
    }

    // ---- epilogue: normalize (l from ones-MMA accumulator), fp16 write
    int b = bh >> 4, h = bh & 15;
#pragma unroll
    for (int rh = 0; rh < 2; rh++) {
        float inv = 1.0f / lacc[rh * 2];
        int t = (qi << 7) + Wm + (lane >> 2) + rh * 8;
        size_t rowbase = ((size_t)(b * Tt + t)) * (Hh * Dd) + h * Dd;
#pragma unroll
        for (int ntd = 0; ntd < 8; ntd++) {
            int d = ntd * 8 + ((lane & 3) << 1);
            *(u32*)(g_a + rowbase + d) =
                packf2(acc2[ntd][rh * 2] * inv, acc2[ntd][rh * 2 + 1] * inv);
        }
    }
}

// ---------------------------------------------------------------------------
extern "C" void kernel_launch(void* const* d_in, const int* in_sizes, int n_in,
                              void* d_out, int out_size) {
    const float* x  = (const float*)d_in[0];
    const float* Wq = (const float*)d_in[1];
    const float* Wk = (const float*)d_in[2];
    const float* Wv = (const float*)d_in[3];
    const float* Wo = (const float*)d_in[4];
    float* out = (float*)d_out;

    cudaFuncSetAttribute(qkv_mma, cudaFuncAttributeMaxDynamicSharedMemorySize, G1_SMEM);
    cudaFuncSetAttribute(out_mma, cudaFuncAttributeMaxDynamicSharedMemorySize, G1_SMEM);
    cudaFuncSetAttribute(attn_mma, cudaFuncAttributeMaxDynamicSharedMemorySize, ATTN_SMEM);

    prep_all<<<12288, 256>>>(x, Wq, Wk, Wv, Wo);
    qkv_mma<<<dim3(24, 64), 256, G1_SMEM>>>();
    attn_mma<<<dim3(Tt / 128, Bb * Hh), 256, ATTN_SMEM>>>();
    out_mma<<<dim3(8, 64), 256, G1_SMEM>>>(out);
}